// round 1
// baseline (speedup 1.0000x reference)
#include <cuda_runtime.h>

#define B_   256
#define L_   512
#define LA_  8
#define LLF_ 64
#define V_   100000
#define D_   300
#define P_   3
#define D4_  75
#define CH_  4

// ---------------- device scratch (no allocations allowed) ----------------
__device__ __align__(16) float g_asp_e[B_ * D_];
__device__ __align__(16) float g_sumvec[B_ * D_];
__device__ __align__(16) float g_matt[B_ * D_];
__device__ float g_w[B_ * L_];
__device__ float g_dot[B_ * L_];
__device__ float g_sw[B_ * L_];
__device__ int   g_len[B_ * 3];   // mem_len, asp_len, left_len
__device__ __align__(16) float g_u[D_];
__device__ __align__(16) float g_p[D_];
__device__ float g_sc[2];         // c = bk.a , constq = bq.b

// ---------------- kernels ----------------
__global__ void zero_kernel() {
    int i = blockIdx.x * blockDim.x + threadIdx.x;
    if (i < B_ * D_) { g_sumvec[i] = 0.f; g_matt[i] = 0.f; }
}

__global__ void prep_kernel(const int* __restrict__ text,
                            const int* __restrict__ aspect,
                            const int* __restrict__ left,
                            const float* __restrict__ embed) {
    int b = blockIdx.x, tid = threadIdx.x;
    __shared__ int cnt[3];
    if (tid < 3) cnt[tid] = 0;
    __syncthreads();
    int c0 = 0;
    for (int l = tid; l < L_; l += 320) c0 += (text[b * L_ + l] != 0);
    int c1 = (tid < LA_) ? (aspect[b * LA_ + tid] != 0) : 0;
    int c2 = 0;
    for (int l = tid; l < LLF_; l += 320) c2 += (left[b * LLF_ + l] != 0);
    if (c0) atomicAdd(&cnt[0], c0);
    if (c1) atomicAdd(&cnt[1], c1);
    if (c2) atomicAdd(&cnt[2], c2);
    __syncthreads();
    int memlen = cnt[0], asplen = cnt[1], leftlen = cnt[2];
    if (tid < 3) g_len[b * 3 + tid] = cnt[tid];

    if (tid < D_) {
        float s = 0.f;
#pragma unroll
        for (int j = 0; j < LA_; j++) {
            int tok = aspect[b * LA_ + j];
            s += embed[(long)tok * D_ + tid];
        }
        g_asp_e[b * D_ + tid] = s / (float)asplen;
    }

    float memf  = (float)memlen;
    float start = (float)(leftlen - asplen);
    float endf  = (float)leftlen;
    for (int l = tid; l < L_; l += 320) {
        float idx = (float)l;
        float lv = idx < start ? (start - idx) : (idx <= endf ? 0.f : idx - endf);
        float wv = 1.f - lv / memf;
        if (!(idx < memf)) wv = 0.f;
        g_w[b * L_ + l] = wv;
    }
}

// folded vector chain: u = Wk@a, c = bk.a, p = Wx^3 @ (Wq@b), constq = bq.b
__global__ void vec_kernel(const float* __restrict__ Wx,
                           const float* __restrict__ Wk,
                           const float* __restrict__ bk,
                           const float* __restrict__ Wq,
                           const float* __restrict__ bq,
                           const float* __restrict__ w_mlp) {
    int tid = threadIdx.x;
    __shared__ float sa[D_], sb[D_], t0[D_], t1[D_];
    __shared__ float rc[2];
    if (tid < 2) rc[tid] = 0.f;
    if (tid < D_) { sa[tid] = w_mlp[tid]; sb[tid] = w_mlp[D_ + tid]; }
    __syncthreads();
    if (tid < D_) {
        float u = 0.f, q = 0.f;
        for (int j = 0; j < D_; j++) {
            u = fmaf(Wk[tid * D_ + j], sa[j], u);
            q = fmaf(Wq[tid * D_ + j], sb[j], q);
        }
        g_u[tid] = u; t0[tid] = q;
        atomicAdd(&rc[0], bk[tid] * sa[tid]);
        atomicAdd(&rc[1], bq[tid] * sb[tid]);
    }
    __syncthreads();
    if (tid < D_) { float s = 0.f; for (int j = 0; j < D_; j++) s = fmaf(Wx[tid * D_ + j], t0[j], s); t1[tid] = s; }
    __syncthreads();
    if (tid < D_) { float s = 0.f; for (int j = 0; j < D_; j++) s = fmaf(Wx[tid * D_ + j], t1[j], s); t0[tid] = s; }
    __syncthreads();
    if (tid < D_) { float s = 0.f; for (int j = 0; j < D_; j++) s = fmaf(Wx[tid * D_ + j], t0[j], s); g_p[tid] = s; }
    if (tid == 0) { g_sc[0] = rc[0]; g_sc[1] = rc[1]; }
}

// pass 1: per token dot(e, u) -> g_dot, and unweighted sum of e -> g_sumvec
__global__ void pass1_kernel(const int* __restrict__ text,
                             const float4* __restrict__ embed4) {
    __shared__ float4 su[D4_];
    __shared__ float red[D_];
    int tid = threadIdx.x;
    if (tid < D4_) su[tid] = reinterpret_cast<const float4*>(g_u)[tid];
    for (int i = tid; i < D_; i += 256) red[i] = 0.f;
    __syncthreads();

    int warp = tid >> 5, lane = tid & 31;
    int b = blockIdx.y;
    const int TOK = (L_ / CH_) / 8;   // 16 tokens per warp
    int l0 = blockIdx.x * (L_ / CH_) + warp * TOK;

    float4 u0 = su[lane], u1 = su[lane + 32];
    float4 u2 = make_float4(0.f, 0.f, 0.f, 0.f);
    if (lane < 11) u2 = su[lane + 64];
    float4 a0 = make_float4(0.f, 0.f, 0.f, 0.f), a1 = a0, a2 = a0;

    int toks[TOK];
#pragma unroll
    for (int t = 0; t < TOK; t++) toks[t] = text[b * L_ + l0 + t];

#pragma unroll 4
    for (int t = 0; t < TOK; t++) {
        const float4* row = embed4 + (long)toks[t] * D4_;
        float4 v0 = row[lane];
        float4 v1 = row[lane + 32];
        float d = v0.x * u0.x + v0.y * u0.y + v0.z * u0.z + v0.w * u0.w
                + v1.x * u1.x + v1.y * u1.y + v1.z * u1.z + v1.w * u1.w;
        a0.x += v0.x; a0.y += v0.y; a0.z += v0.z; a0.w += v0.w;
        a1.x += v1.x; a1.y += v1.y; a1.z += v1.z; a1.w += v1.w;
        if (lane < 11) {
            float4 v2 = row[lane + 64];
            d += v2.x * u2.x + v2.y * u2.y + v2.z * u2.z + v2.w * u2.w;
            a2.x += v2.x; a2.y += v2.y; a2.z += v2.z; a2.w += v2.w;
        }
#pragma unroll
        for (int off = 16; off; off >>= 1) d += __shfl_xor_sync(0xffffffffu, d, off);
        if (lane == 0) g_dot[b * L_ + l0 + t] = d;
    }

    atomicAdd(&red[4 * lane + 0], a0.x); atomicAdd(&red[4 * lane + 1], a0.y);
    atomicAdd(&red[4 * lane + 2], a0.z); atomicAdd(&red[4 * lane + 3], a0.w);
    atomicAdd(&red[128 + 4 * lane + 0], a1.x); atomicAdd(&red[128 + 4 * lane + 1], a1.y);
    atomicAdd(&red[128 + 4 * lane + 2], a1.z); atomicAdd(&red[128 + 4 * lane + 3], a1.w);
    if (lane < 11) {
        atomicAdd(&red[256 + 4 * lane + 0], a2.x); atomicAdd(&red[256 + 4 * lane + 1], a2.y);
        atomicAdd(&red[256 + 4 * lane + 2], a2.z); atomicAdd(&red[256 + 4 * lane + 3], a2.w);
    }
    __syncthreads();
    for (int i = tid; i < D_; i += 256) atomicAdd(&g_sumvec[b * D_ + i], red[i]);
}

// per-batch: qs, tanh, softmax over L, store score*w
__global__ void softmax_kernel() {
    int b = blockIdx.x, tid = threadIdx.x;
    __shared__ float red[512];
    float part = (tid < D_) ? g_asp_e[b * D_ + tid] * g_p[tid] : 0.f;
    red[tid] = part; __syncthreads();
    for (int s = 256; s; s >>= 1) { if (tid < s) red[tid] += red[tid + s]; __syncthreads(); }
    float qs = red[0] + g_sc[1];
    float cc = g_sc[0];
    __syncthreads();

    float wv = g_w[b * L_ + tid];
    float logit = tanhf(g_dot[b * L_ + tid] * wv + cc + qs);

    red[tid] = logit; __syncthreads();
    for (int s = 256; s; s >>= 1) { if (tid < s) red[tid] = fmaxf(red[tid], red[tid + s]); __syncthreads(); }
    float m = red[0]; __syncthreads();
    float e = expf(logit - m);
    red[tid] = e; __syncthreads();
    for (int s = 256; s; s >>= 1) { if (tid < s) red[tid] += red[tid + s]; __syncthreads(); }
    float inv = 1.f / red[0];
    g_sw[b * L_ + tid] = e * inv * wv;
}

// pass 2: m_att[b] = sum_l sw[b,l] * embed[text[b,l]]
__global__ void pass2_kernel(const int* __restrict__ text,
                             const float4* __restrict__ embed4) {
    __shared__ float red[D_];
    int tid = threadIdx.x;
    for (int i = tid; i < D_; i += 256) red[i] = 0.f;
    __syncthreads();

    int warp = tid >> 5, lane = tid & 31;
    int b = blockIdx.y;
    const int TOK = (L_ / CH_) / 8;
    int l0 = blockIdx.x * (L_ / CH_) + warp * TOK;

    float4 a0 = make_float4(0.f, 0.f, 0.f, 0.f), a1 = a0, a2 = a0;

#pragma unroll 4
    for (int t = 0; t < TOK; t++) {
        int l = l0 + t;
        float swv = g_sw[b * L_ + l];
        if (swv != 0.f) {
            int tok = text[b * L_ + l];
            const float4* row = embed4 + (long)tok * D4_;
            float4 v0 = row[lane];
            float4 v1 = row[lane + 32];
            a0.x = fmaf(swv, v0.x, a0.x); a0.y = fmaf(swv, v0.y, a0.y);
            a0.z = fmaf(swv, v0.z, a0.z); a0.w = fmaf(swv, v0.w, a0.w);
            a1.x = fmaf(swv, v1.x, a1.x); a1.y = fmaf(swv, v1.y, a1.y);
            a1.z = fmaf(swv, v1.z, a1.z); a1.w = fmaf(swv, v1.w, a1.w);
            if (lane < 11) {
                float4 v2 = row[lane + 64];
                a2.x = fmaf(swv, v2.x, a2.x); a2.y = fmaf(swv, v2.y, a2.y);
                a2.z = fmaf(swv, v2.z, a2.z); a2.w = fmaf(swv, v2.w, a2.w);
            }
        }
    }

    atomicAdd(&red[4 * lane + 0], a0.x); atomicAdd(&red[4 * lane + 1], a0.y);
    atomicAdd(&red[4 * lane + 2], a0.z); atomicAdd(&red[4 * lane + 3], a0.w);
    atomicAdd(&red[128 + 4 * lane + 0], a1.x); atomicAdd(&red[128 + 4 * lane + 1], a1.y);
    atomicAdd(&red[128 + 4 * lane + 2], a1.z); atomicAdd(&red[128 + 4 * lane + 3], a1.w);
    if (lane < 11) {
        atomicAdd(&red[256 + 4 * lane + 0], a2.x); atomicAdd(&red[256 + 4 * lane + 1], a2.y);
        atomicAdd(&red[256 + 4 * lane + 2], a2.z); atomicAdd(&red[256 + 4 * lane + 3], a2.w);
    }
    __syncthreads();
    for (int i = tid; i < D_; i += 256) atomicAdd(&g_matt[b * D_ + i], red[i]);
}

// head: v_ts = m_att@Wk+bk; @Wproj+bproj; +v_s; tanh(@Wm+bm); softmax(@Wd+bd)
__global__ void head_kernel(const float* __restrict__ Wk, const float* __restrict__ bk,
                            const float* __restrict__ Wproj, const float* __restrict__ bproj,
                            const float* __restrict__ Wm, const float* __restrict__ bm,
                            const float* __restrict__ Wd, const float* __restrict__ bd,
                            float* __restrict__ out) {
    const int R = 4;
    int b0 = blockIdx.x * R, tid = threadIdx.x;
    __shared__ float s_in[R][D_];
    __shared__ float s_out[R][D_];
    __shared__ float slog[R][P_];

    for (int i = tid; i < R * D_; i += 320)
        s_in[i / D_][i % D_] = g_matt[(b0 + i / D_) * D_ + (i % D_)];
    __syncthreads();

    float acc[R];
    if (tid < D_) {
#pragma unroll
        for (int r = 0; r < R; r++) acc[r] = bk[tid];
        for (int d = 0; d < D_; d++) {
            float wv = Wk[d * D_ + tid];
#pragma unroll
            for (int r = 0; r < R; r++) acc[r] = fmaf(s_in[r][d], wv, acc[r]);
        }
#pragma unroll
        for (int r = 0; r < R; r++) s_out[r][tid] = acc[r];
    }
    __syncthreads();
    if (tid < D_) {
#pragma unroll
        for (int r = 0; r < R; r++) acc[r] = bproj[tid];
        for (int d = 0; d < D_; d++) {
            float wv = Wproj[d * D_ + tid];
#pragma unroll
            for (int r = 0; r < R; r++) acc[r] = fmaf(s_out[r][d], wv, acc[r]);
        }
#pragma unroll
        for (int r = 0; r < R; r++) {
            float vs = g_sumvec[(b0 + r) * D_ + tid] / (float)g_len[(b0 + r) * 3 + 0];
            s_in[r][tid] = acc[r] + vs;
        }
    }
    __syncthreads();
    if (tid < D_) {
#pragma unroll
        for (int r = 0; r < R; r++) acc[r] = bm[tid];
        for (int d = 0; d < D_; d++) {
            float wv = Wm[d * D_ + tid];
#pragma unroll
            for (int r = 0; r < R; r++) acc[r] = fmaf(s_in[r][d], wv, acc[r]);
        }
#pragma unroll
        for (int r = 0; r < R; r++) s_out[r][tid] = tanhf(acc[r]);
    }
    __syncthreads();
    if (tid < R * P_) {
        int r = tid / P_, p = tid % P_;
        float s = bd[p];
        for (int d = 0; d < D_; d++) s = fmaf(s_out[r][d], Wd[d * P_ + p], s);
        slog[r][p] = s;
    }
    __syncthreads();
    if (tid < R) {
        int r = tid;
        float m = fmaxf(slog[r][0], fmaxf(slog[r][1], slog[r][2]));
        float e0 = expf(slog[r][0] - m), e1 = expf(slog[r][1] - m), e2 = expf(slog[r][2] - m);
        float inv = 1.f / (e0 + e1 + e2);
        out[(b0 + r) * P_ + 0] = e0 * inv;
        out[(b0 + r) * P_ + 1] = e1 * inv;
        out[(b0 + r) * P_ + 2] = e2 * inv;
    }
}

extern "C" void kernel_launch(void* const* d_in, const int* in_sizes, int n_in,
                              void* d_out, int out_size) {
    const int*   text   = (const int*)d_in[0];
    const int*   aspect = (const int*)d_in[1];
    const int*   left   = (const int*)d_in[2];
    const float* embed  = (const float*)d_in[3];
    const float* Wx     = (const float*)d_in[4];
    // d_in[5] = Ws (dead in reference)
    const float* Wk     = (const float*)d_in[6];
    const float* bk     = (const float*)d_in[7];
    const float* Wq     = (const float*)d_in[8];
    const float* bq     = (const float*)d_in[9];
    const float* w_mlp  = (const float*)d_in[10];
    const float* Wproj  = (const float*)d_in[11];
    const float* bproj  = (const float*)d_in[12];
    const float* Wm     = (const float*)d_in[13];
    const float* bm     = (const float*)d_in[14];
    const float* Wd     = (const float*)d_in[15];
    const float* bd     = (const float*)d_in[16];
    float* out = (float*)d_out;

    zero_kernel<<<(B_ * D_ + 255) / 256, 256>>>();
    prep_kernel<<<B_, 320>>>(text, aspect, left, embed);
    vec_kernel<<<1, 320>>>(Wx, Wk, bk, Wq, bq, w_mlp);
    pass1_kernel<<<dim3(CH_, B_), 256>>>(text, (const float4*)embed);
    softmax_kernel<<<B_, 512>>>();
    pass2_kernel<<<dim3(CH_, B_), 256>>>(text, (const float4*)embed);
    head_kernel<<<B_ / 4, 320>>>(Wk, bk, Wproj, bproj, Wm, bm, Wd, bd, out);
}

// round 2
// speedup vs baseline: 1.0770x; 1.0770x over previous
#include <cuda_runtime.h>

#define B_   256
#define L_   512
#define LA_  8
#define LLF_ 64
#define V_   100000
#define D_   300
#define P_   3
#define D4_  75
#define CH_  8

// ---------------- device scratch (no allocations allowed) ----------------
__device__ __align__(16) float g_asp_e[B_ * D_];
__device__ __align__(16) float g_sumvec[B_ * D_];
__device__ __align__(16) float g_matt[B_ * D_];
__device__ float g_w[B_ * L_];
__device__ float g_dot[B_ * L_];
__device__ float g_sw[B_ * L_];
__device__ int   g_len[B_ * 3];   // mem_len, asp_len, left_len
__device__ __align__(16) float g_u[D_];
__device__ __align__(16) float g_p[D_];
__device__ float g_sc[2];         // c = bk.a , constq = bq.b

// ---------------- kernels ----------------
__global__ void prep_kernel(const int* __restrict__ text,
                            const int* __restrict__ aspect,
                            const int* __restrict__ left,
                            const float* __restrict__ embed) {
    int b = blockIdx.x, tid = threadIdx.x;
    __shared__ int cnt[3];
    if (tid < 3) cnt[tid] = 0;
    // zero the accumulators for pass1/pass2 (was zero_kernel)
    for (int i = tid; i < D_; i += 320) {
        g_sumvec[b * D_ + i] = 0.f;
        g_matt[b * D_ + i] = 0.f;
    }
    __syncthreads();
    int c0 = 0;
    for (int l = tid; l < L_; l += 320) c0 += (text[b * L_ + l] != 0);
    int c1 = (tid < LA_) ? (aspect[b * LA_ + tid] != 0) : 0;
    int c2 = 0;
    for (int l = tid; l < LLF_; l += 320) c2 += (left[b * LLF_ + l] != 0);
    if (c0) atomicAdd(&cnt[0], c0);
    if (c1) atomicAdd(&cnt[1], c1);
    if (c2) atomicAdd(&cnt[2], c2);
    __syncthreads();
    int memlen = cnt[0], asplen = cnt[1], leftlen = cnt[2];
    if (tid < 3) g_len[b * 3 + tid] = cnt[tid];

    if (tid < D_) {
        float s = 0.f;
#pragma unroll
        for (int j = 0; j < LA_; j++) {
            int tok = aspect[b * LA_ + j];
            s += embed[(long)tok * D_ + tid];
        }
        g_asp_e[b * D_ + tid] = s / (float)asplen;
    }

    float memf  = (float)memlen;
    float start = (float)(leftlen - asplen);
    float endf  = (float)leftlen;
    for (int l = tid; l < L_; l += 320) {
        float idx = (float)l;
        float lv = idx < start ? (start - idx) : (idx <= endf ? 0.f : idx - endf);
        float wv = 1.f - lv / memf;
        if (!(idx < memf)) wv = 0.f;
        g_w[b * L_ + l] = wv;
    }
}

// folded vector chain: u = Wk@a, c = bk.a, p = Wx^3 @ (Wq@b), constq = bq.b
// warp-per-row, coalesced lane-strided row reads + shuffle reduction
__global__ void vec_kernel(const float* __restrict__ Wx,
                           const float* __restrict__ Wk,
                           const float* __restrict__ bk,
                           const float* __restrict__ Wq,
                           const float* __restrict__ bq,
                           const float* __restrict__ w_mlp) {
    int tid = threadIdx.x, warp = tid >> 5, lane = tid & 31;
    __shared__ float sa[D_], sb[D_], t0[D_], t1[D_];
    for (int i = tid; i < D_; i += 320) { sa[i] = w_mlp[i]; sb[i] = w_mlp[D_ + i]; }
    __syncthreads();

    // phase A: u = Wk@a, q = Wq@b (rows coalesced per warp)
    for (int row = warp; row < D_; row += 10) {
        float u = 0.f, q = 0.f;
        for (int j = lane; j < D_; j += 32) {
            u = fmaf(Wk[row * D_ + j], sa[j], u);
            q = fmaf(Wq[row * D_ + j], sb[j], q);
        }
#pragma unroll
        for (int off = 16; off; off >>= 1) {
            u += __shfl_xor_sync(0xffffffffu, u, off);
            q += __shfl_xor_sync(0xffffffffu, q, off);
        }
        if (lane == 0) { g_u[row] = u; t0[row] = q; }
    }
    if (warp == 0) {
        float s = 0.f;
        for (int j = lane; j < D_; j += 32) s = fmaf(bk[j], sa[j], s);
#pragma unroll
        for (int off = 16; off; off >>= 1) s += __shfl_xor_sync(0xffffffffu, s, off);
        if (lane == 0) g_sc[0] = s;
    }
    if (warp == 1) {
        float s = 0.f;
        for (int j = lane; j < D_; j += 32) s = fmaf(bq[j], sb[j], s);
#pragma unroll
        for (int off = 16; off; off >>= 1) s += __shfl_xor_sync(0xffffffffu, s, off);
        if (lane == 0) g_sc[1] = s;
    }
    __syncthreads();

    // phase B: t1 = Wx @ t0
    for (int row = warp; row < D_; row += 10) {
        float s = 0.f;
        for (int j = lane; j < D_; j += 32) s = fmaf(Wx[row * D_ + j], t0[j], s);
#pragma unroll
        for (int off = 16; off; off >>= 1) s += __shfl_xor_sync(0xffffffffu, s, off);
        if (lane == 0) t1[row] = s;
    }
    __syncthreads();

    // phase C: t0 = Wx @ t1
    for (int row = warp; row < D_; row += 10) {
        float s = 0.f;
        for (int j = lane; j < D_; j += 32) s = fmaf(Wx[row * D_ + j], t1[j], s);
#pragma unroll
        for (int off = 16; off; off >>= 1) s += __shfl_xor_sync(0xffffffffu, s, off);
        if (lane == 0) t0[row] = s;
    }
    __syncthreads();

    // phase D: g_p = Wx @ t0
    for (int row = warp; row < D_; row += 10) {
        float s = 0.f;
        for (int j = lane; j < D_; j += 32) s = fmaf(Wx[row * D_ + j], t0[j], s);
#pragma unroll
        for (int off = 16; off; off >>= 1) s += __shfl_xor_sync(0xffffffffu, s, off);
        if (lane == 0) g_p[row] = s;
    }
}

// pass 1: per token dot(e, u) -> g_dot, and unweighted sum of e -> g_sumvec
__global__ void pass1_kernel(const int* __restrict__ text,
                             const float4* __restrict__ embed4) {
    __shared__ float4 su[D4_];
    __shared__ float red[D_];
    int tid = threadIdx.x;
    if (tid < D4_) su[tid] = reinterpret_cast<const float4*>(g_u)[tid];
    for (int i = tid; i < D_; i += 256) red[i] = 0.f;
    __syncthreads();

    int warp = tid >> 5, lane = tid & 31;
    int b = blockIdx.y;
    const int TOK = (L_ / CH_) / 8;   // 8 tokens per warp
    int l0 = blockIdx.x * (L_ / CH_) + warp * TOK;

    float4 u0 = su[lane], u1 = su[lane + 32];
    float4 u2 = make_float4(0.f, 0.f, 0.f, 0.f);
    if (lane < 11) u2 = su[lane + 64];
    float4 a0 = make_float4(0.f, 0.f, 0.f, 0.f), a1 = a0, a2 = a0;

    int toks[TOK];
#pragma unroll
    for (int t = 0; t < TOK; t++) toks[t] = text[b * L_ + l0 + t];

#pragma unroll
    for (int t = 0; t < TOK; t++) {
        const float4* row = embed4 + (long)toks[t] * D4_;
        float4 v0 = row[lane];
        float4 v1 = row[lane + 32];
        float d = v0.x * u0.x + v0.y * u0.y + v0.z * u0.z + v0.w * u0.w
                + v1.x * u1.x + v1.y * u1.y + v1.z * u1.z + v1.w * u1.w;
        a0.x += v0.x; a0.y += v0.y; a0.z += v0.z; a0.w += v0.w;
        a1.x += v1.x; a1.y += v1.y; a1.z += v1.z; a1.w += v1.w;
        if (lane < 11) {
            float4 v2 = row[lane + 64];
            d += v2.x * u2.x + v2.y * u2.y + v2.z * u2.z + v2.w * u2.w;
            a2.x += v2.x; a2.y += v2.y; a2.z += v2.z; a2.w += v2.w;
        }
#pragma unroll
        for (int off = 16; off; off >>= 1) d += __shfl_xor_sync(0xffffffffu, d, off);
        if (lane == 0) g_dot[b * L_ + l0 + t] = d;
    }

    atomicAdd(&red[4 * lane + 0], a0.x); atomicAdd(&red[4 * lane + 1], a0.y);
    atomicAdd(&red[4 * lane + 2], a0.z); atomicAdd(&red[4 * lane + 3], a0.w);
    atomicAdd(&red[128 + 4 * lane + 0], a1.x); atomicAdd(&red[128 + 4 * lane + 1], a1.y);
    atomicAdd(&red[128 + 4 * lane + 2], a1.z); atomicAdd(&red[128 + 4 * lane + 3], a1.w);
    if (lane < 11) {
        atomicAdd(&red[256 + 4 * lane + 0], a2.x); atomicAdd(&red[256 + 4 * lane + 1], a2.y);
        atomicAdd(&red[256 + 4 * lane + 2], a2.z); atomicAdd(&red[256 + 4 * lane + 3], a2.w);
    }
    __syncthreads();
    for (int i = tid; i < D_; i += 256) atomicAdd(&g_sumvec[b * D_ + i], red[i]);
}

// per-batch: qs, tanh, softmax over L, store score*w
__global__ void softmax_kernel() {
    int b = blockIdx.x, tid = threadIdx.x;
    __shared__ float red[512];
    float part = (tid < D_) ? g_asp_e[b * D_ + tid] * g_p[tid] : 0.f;
    red[tid] = part; __syncthreads();
    for (int s = 256; s; s >>= 1) { if (tid < s) red[tid] += red[tid + s]; __syncthreads(); }
    float qs = red[0] + g_sc[1];
    float cc = g_sc[0];
    __syncthreads();

    float wv = g_w[b * L_ + tid];
    float logit = tanhf(g_dot[b * L_ + tid] * wv + cc + qs);

    red[tid] = logit; __syncthreads();
    for (int s = 256; s; s >>= 1) { if (tid < s) red[tid] = fmaxf(red[tid], red[tid + s]); __syncthreads(); }
    float m = red[0]; __syncthreads();
    float e = expf(logit - m);
    red[tid] = e; __syncthreads();
    for (int s = 256; s; s >>= 1) { if (tid < s) red[tid] += red[tid + s]; __syncthreads(); }
    float inv = 1.f / red[0];
    g_sw[b * L_ + tid] = e * inv * wv;
}

// pass 2: m_att[b] = sum_l sw[b,l] * embed[text[b,l]]
__global__ void pass2_kernel(const int* __restrict__ text,
                             const float4* __restrict__ embed4) {
    __shared__ float red[D_];
    int tid = threadIdx.x;
    for (int i = tid; i < D_; i += 256) red[i] = 0.f;
    __syncthreads();

    int warp = tid >> 5, lane = tid & 31;
    int b = blockIdx.y;
    const int TOK = (L_ / CH_) / 8;
    int l0 = blockIdx.x * (L_ / CH_) + warp * TOK;

    float4 a0 = make_float4(0.f, 0.f, 0.f, 0.f), a1 = a0, a2 = a0;

#pragma unroll
    for (int t = 0; t < TOK; t++) {
        int l = l0 + t;
        float swv = g_sw[b * L_ + l];
        if (swv != 0.f) {
            int tok = text[b * L_ + l];
            const float4* row = embed4 + (long)tok * D4_;
            float4 v0 = row[lane];
            float4 v1 = row[lane + 32];
            a0.x = fmaf(swv, v0.x, a0.x); a0.y = fmaf(swv, v0.y, a0.y);
            a0.z = fmaf(swv, v0.z, a0.z); a0.w = fmaf(swv, v0.w, a0.w);
            a1.x = fmaf(swv, v1.x, a1.x); a1.y = fmaf(swv, v1.y, a1.y);
            a1.z = fmaf(swv, v1.z, a1.z); a1.w = fmaf(swv, v1.w, a1.w);
            if (lane < 11) {
                float4 v2 = row[lane + 64];
                a2.x = fmaf(swv, v2.x, a2.x); a2.y = fmaf(swv, v2.y, a2.y);
                a2.z = fmaf(swv, v2.z, a2.z); a2.w = fmaf(swv, v2.w, a2.w);
            }
        }
    }

    atomicAdd(&red[4 * lane + 0], a0.x); atomicAdd(&red[4 * lane + 1], a0.y);
    atomicAdd(&red[4 * lane + 2], a0.z); atomicAdd(&red[4 * lane + 3], a0.w);
    atomicAdd(&red[128 + 4 * lane + 0], a1.x); atomicAdd(&red[128 + 4 * lane + 1], a1.y);
    atomicAdd(&red[128 + 4 * lane + 2], a1.z); atomicAdd(&red[128 + 4 * lane + 3], a1.w);
    if (lane < 11) {
        atomicAdd(&red[256 + 4 * lane + 0], a2.x); atomicAdd(&red[256 + 4 * lane + 1], a2.y);
        atomicAdd(&red[256 + 4 * lane + 2], a2.z); atomicAdd(&red[256 + 4 * lane + 3], a2.w);
    }
    __syncthreads();
    for (int i = tid; i < D_; i += 256) atomicAdd(&g_matt[b * D_ + i], red[i]);
}

// head: v_ts = m_att@Wk+bk; @Wproj+bproj; +v_s; tanh(@Wm+bm); softmax(@Wd+bd)
__global__ void head_kernel(const float* __restrict__ Wk, const float* __restrict__ bk,
                            const float* __restrict__ Wproj, const float* __restrict__ bproj,
                            const float* __restrict__ Wm, const float* __restrict__ bm,
                            const float* __restrict__ Wd, const float* __restrict__ bd,
                            float* __restrict__ out) {
    const int R = 4;
    int b0 = blockIdx.x * R, tid = threadIdx.x;
    __shared__ float s_in[R][D_];
    __shared__ float s_out[R][D_];
    __shared__ float slog[R][P_];

    for (int i = tid; i < R * D_; i += 320)
        s_in[i / D_][i % D_] = g_matt[(b0 + i / D_) * D_ + (i % D_)];
    __syncthreads();

    float acc[R];
    if (tid < D_) {
#pragma unroll
        for (int r = 0; r < R; r++) acc[r] = bk[tid];
        for (int d = 0; d < D_; d++) {
            float wv = Wk[d * D_ + tid];
#pragma unroll
            for (int r = 0; r < R; r++) acc[r] = fmaf(s_in[r][d], wv, acc[r]);
        }
#pragma unroll
        for (int r = 0; r < R; r++) s_out[r][tid] = acc[r];
    }
    __syncthreads();
    if (tid < D_) {
#pragma unroll
        for (int r = 0; r < R; r++) acc[r] = bproj[tid];
        for (int d = 0; d < D_; d++) {
            float wv = Wproj[d * D_ + tid];
#pragma unroll
            for (int r = 0; r < R; r++) acc[r] = fmaf(s_out[r][d], wv, acc[r]);
        }
#pragma unroll
        for (int r = 0; r < R; r++) {
            float vs = g_sumvec[(b0 + r) * D_ + tid] / (float)g_len[(b0 + r) * 3 + 0];
            s_in[r][tid] = acc[r] + vs;
        }
    }
    __syncthreads();
    if (tid < D_) {
#pragma unroll
        for (int r = 0; r < R; r++) acc[r] = bm[tid];
        for (int d = 0; d < D_; d++) {
            float wv = Wm[d * D_ + tid];
#pragma unroll
            for (int r = 0; r < R; r++) acc[r] = fmaf(s_in[r][d], wv, acc[r]);
        }
#pragma unroll
        for (int r = 0; r < R; r++) s_out[r][tid] = tanhf(acc[r]);
    }
    __syncthreads();
    if (tid < R * P_) {
        int r = tid / P_, p = tid % P_;
        float s = bd[p];
        for (int d = 0; d < D_; d++) s = fmaf(s_out[r][d], Wd[d * P_ + p], s);
        slog[r][p] = s;
    }
    __syncthreads();
    if (tid < R) {
        int r = tid;
        float m = fmaxf(slog[r][0], fmaxf(slog[r][1], slog[r][2]));
        float e0 = expf(slog[r][0] - m), e1 = expf(slog[r][1] - m), e2 = expf(slog[r][2] - m);
        float inv = 1.f / (e0 + e1 + e2);
        out[(b0 + r) * P_ + 0] = e0 * inv;
        out[(b0 + r) * P_ + 1] = e1 * inv;
        out[(b0 + r) * P_ + 2] = e2 * inv;
    }
}

extern "C" void kernel_launch(void* const* d_in, const int* in_sizes, int n_in,
                              void* d_out, int out_size) {
    const int*   text   = (const int*)d_in[0];
    const int*   aspect = (const int*)d_in[1];
    const int*   left   = (const int*)d_in[2];
    const float* embed  = (const float*)d_in[3];
    const float* Wx     = (const float*)d_in[4];
    // d_in[5] = Ws (dead in reference)
    const float* Wk     = (const float*)d_in[6];
    const float* bk     = (const float*)d_in[7];
    const float* Wq     = (const float*)d_in[8];
    const float* bq     = (const float*)d_in[9];
    const float* w_mlp  = (const float*)d_in[10];
    const float* Wproj  = (const float*)d_in[11];
    const float* bproj  = (const float*)d_in[12];
    const float* Wm     = (const float*)d_in[13];
    const float* bm     = (const float*)d_in[14];
    const float* Wd     = (const float*)d_in[15];
    const float* bd     = (const float*)d_in[16];
    float* out = (float*)d_out;

    prep_kernel<<<B_, 320>>>(text, aspect, left, embed);
    vec_kernel<<<1, 320>>>(Wx, Wk, bk, Wq, bq, w_mlp);
    pass1_kernel<<<dim3(CH_, B_), 256>>>(text, (const float4*)embed);
    softmax_kernel<<<B_, 512>>>();
    pass2_kernel<<<dim3(CH_, B_), 256>>>(text, (const float4*)embed);
    head_kernel<<<B_ / 4, 320>>>(Wk, bk, Wproj, bproj, Wm, bm, Wd, bd, out);
}

// round 3
// speedup vs baseline: 1.2537x; 1.1641x over previous
#include <cuda_runtime.h>

#define B_   256
#define L_   512
#define LA_  8
#define LLF_ 64
#define V_   100000
#define D_   300
#define P_   3
#define D4_  75
#define CH_  8

// ---------------- device scratch ----------------
__device__ __align__(16) float g_asp_e[B_ * D_];
__device__ __align__(16) float g_sumvec[B_ * D_];
__device__ __align__(16) float g_matt[B_ * D_];
__device__ float g_w[B_ * L_];
__device__ float g_dot[B_ * L_];
__device__ int   g_len[B_ * 3];   // mem_len, asp_len, left_len
__device__ __align__(16) float g_u[D_];
__device__ __align__(16) float g_t0[D_];
__device__ __align__(16) float g_t1[D_];
__device__ __align__(16) float g_p[D_];
__device__ float g_sc[2];         // c = bk.a , constq = bq.b
__device__ float g_qs[B_];

// ---------------- prep: lengths, w, aspect embedding, zero accum ----------------
__global__ void prep_kernel(const int* __restrict__ text,
                            const int* __restrict__ aspect,
                            const int* __restrict__ left,
                            const float* __restrict__ embed) {
    int b = blockIdx.x, tid = threadIdx.x;
    __shared__ int cnt[3];
    if (tid < 3) cnt[tid] = 0;
    for (int i = tid; i < D_; i += 320) {
        g_sumvec[b * D_ + i] = 0.f;
        g_matt[b * D_ + i] = 0.f;
    }
    __syncthreads();
    int c0 = 0;
    for (int l = tid; l < L_; l += 320) c0 += (text[b * L_ + l] != 0);
    int c1 = (tid < LA_) ? (aspect[b * LA_ + tid] != 0) : 0;
    int c2 = 0;
    for (int l = tid; l < LLF_; l += 320) c2 += (left[b * LLF_ + l] != 0);
    if (c0) atomicAdd(&cnt[0], c0);
    if (c1) atomicAdd(&cnt[1], c1);
    if (c2) atomicAdd(&cnt[2], c2);
    __syncthreads();
    int memlen = cnt[0], asplen = cnt[1], leftlen = cnt[2];
    if (tid < 3) g_len[b * 3 + tid] = cnt[tid];

    if (tid < D_) {
        float s = 0.f;
#pragma unroll
        for (int j = 0; j < LA_; j++) {
            int tok = aspect[b * LA_ + j];
            s += embed[(long)tok * D_ + tid];
        }
        g_asp_e[b * D_ + tid] = s / (float)asplen;
    }

    float memf  = (float)memlen;
    float start = (float)(leftlen - asplen);
    float endf  = (float)leftlen;
    for (int l = tid; l < L_; l += 320) {
        float idx = (float)l;
        float lv = idx < start ? (start - idx) : (idx <= endf ? 0.f : idx - endf);
        float wv = 1.f - lv / memf;
        if (!(idx < memf)) wv = 0.f;
        g_w[b * L_ + l] = wv;
    }
}

// ---------------- vecA: u = Wk@a, t0 = Wq@b, scalars (warp per row, wide grid) ---
__global__ void vecA_kernel(const float* __restrict__ Wk,
                            const float* __restrict__ bk,
                            const float* __restrict__ Wq,
                            const float* __restrict__ bq,
                            const float* __restrict__ w_mlp) {
    int warp = threadIdx.x >> 5, lane = threadIdx.x & 31;
    int gw = blockIdx.x * 10 + warp;
    if (gw < D_) {
        float u = 0.f, q = 0.f;
        for (int j = lane; j < D_; j += 32) {
            u = fmaf(Wk[gw * D_ + j], w_mlp[j], u);
            q = fmaf(Wq[gw * D_ + j], w_mlp[D_ + j], q);
        }
#pragma unroll
        for (int off = 16; off; off >>= 1) {
            u += __shfl_xor_sync(0xffffffffu, u, off);
            q += __shfl_xor_sync(0xffffffffu, q, off);
        }
        if (lane == 0) { g_u[gw] = u; g_t0[gw] = q; }
    } else if (gw == D_ || gw == D_ + 1) {
        const float* v1 = (gw == D_) ? bk : bq;
        const float* v2 = (gw == D_) ? w_mlp : (w_mlp + D_);
        float s = 0.f;
        for (int j = lane; j < D_; j += 32) s = fmaf(v1[j], v2[j], s);
#pragma unroll
        for (int off = 16; off; off >>= 1) s += __shfl_xor_sync(0xffffffffu, s, off);
        if (lane == 0) g_sc[gw - D_] = s;
    }
}

// ---------------- matvec: out = Wx @ in (warp per row) ----------------
__global__ void mv_kernel(const float* __restrict__ Wx, int step) {
    const float* in  = (step == 1) ? g_t1 : g_t0;
    float*       out = (step == 0) ? g_t1 : ((step == 1) ? g_t0 : g_p);
    int warp = threadIdx.x >> 5, lane = threadIdx.x & 31;
    int row = blockIdx.x * 10 + warp;
    if (row >= D_) return;
    float s = 0.f;
    for (int j = lane; j < D_; j += 32) s = fmaf(Wx[row * D_ + j], in[j], s);
#pragma unroll
    for (int off = 16; off; off >>= 1) s += __shfl_xor_sync(0xffffffffu, s, off);
    if (lane == 0) out[row] = s;
}

// ---------------- qs[b] = asp_e[b]·p + constq (warp per batch row) -------------
__global__ void qs_kernel() {
    int warp = threadIdx.x >> 5, lane = threadIdx.x & 31;
    int b = blockIdx.x * 10 + warp;
    if (b >= B_) return;
    float s = 0.f;
    for (int j = lane; j < D_; j += 32) s = fmaf(g_asp_e[b * D_ + j], g_p[j], s);
#pragma unroll
    for (int off = 16; off; off >>= 1) s += __shfl_xor_sync(0xffffffffu, s, off);
    if (lane == 0) g_qs[b] = s + g_sc[1];
}

// ---------------- pass1: dot(e,u) per token + raw row sum ----------------
// 16 lanes per token row, 2 tokens per warp iteration.
__global__ void pass1_kernel(const int* __restrict__ text,
                             const float4* __restrict__ embed4) {
    __shared__ float4 su[D4_ + 1];
    __shared__ float red[D_];
    int tid = threadIdx.x;
    if (tid < D4_) su[tid] = reinterpret_cast<const float4*>(g_u)[tid];
    if (tid == D4_) su[D4_] = make_float4(0.f, 0.f, 0.f, 0.f);
    for (int i = tid; i < D_; i += 256) red[i] = 0.f;
    __syncthreads();

    int warp = tid >> 5, lane = tid & 31;
    int half = lane >> 4, sub = lane & 15;
    int b = blockIdx.y;
    int l0 = blockIdx.x * (L_ / CH_) + warp * 8;   // 8 tokens per warp

    // per-thread slice of u: float4 indices sub+16k (k=0..4; k=4 only sub<11)
    float4 u0 = su[sub], u1 = su[sub + 16], u2 = su[sub + 32], u3 = su[sub + 48];
    float4 u4 = (sub < 11) ? su[sub + 64] : make_float4(0.f, 0.f, 0.f, 0.f);
    int last = (sub < 11) ? (sub + 64) : D4_;   // D4_ slot is zeroed pad

    float4 a0 = make_float4(0.f,0.f,0.f,0.f), a1 = a0, a2 = a0, a3 = a0, a4 = a0;

    int toks[8];
#pragma unroll
    for (int t = 0; t < 8; t++) toks[t] = text[b * L_ + l0 + t];

#pragma unroll
    for (int pr = 0; pr < 4; pr++) {
        int tok = toks[2 * pr + half];
        const float4* row = embed4 + (long)tok * D4_;
        float4 v0 = row[sub];
        float4 v1 = row[sub + 16];
        float4 v2 = row[sub + 32];
        float4 v3 = row[sub + 48];
        float4 v4 = row[last];
        if (sub >= 11) v4 = make_float4(0.f, 0.f, 0.f, 0.f);

        float d = v0.x*u0.x + v0.y*u0.y + v0.z*u0.z + v0.w*u0.w
                + v1.x*u1.x + v1.y*u1.y + v1.z*u1.z + v1.w*u1.w
                + v2.x*u2.x + v2.y*u2.y + v2.z*u2.z + v2.w*u2.w
                + v3.x*u3.x + v3.y*u3.y + v3.z*u3.z + v3.w*u3.w
                + v4.x*u4.x + v4.y*u4.y + v4.z*u4.z + v4.w*u4.w;

        a0.x += v0.x; a0.y += v0.y; a0.z += v0.z; a0.w += v0.w;
        a1.x += v1.x; a1.y += v1.y; a1.z += v1.z; a1.w += v1.w;
        a2.x += v2.x; a2.y += v2.y; a2.z += v2.z; a2.w += v2.w;
        a3.x += v3.x; a3.y += v3.y; a3.z += v3.z; a3.w += v3.w;
        a4.x += v4.x; a4.y += v4.y; a4.z += v4.z; a4.w += v4.w;

        // reduce within 16-lane group (both halves in parallel)
#pragma unroll
        for (int off = 8; off; off >>= 1) d += __shfl_xor_sync(0xffffffffu, d, off);
        if (sub == 0) g_dot[b * L_ + l0 + 2 * pr + half] = d;
    }

    // block-level reduction of raw-row sums
    {
        int p0 = 4 * sub;
        atomicAdd(&red[p0 + 0], a0.x); atomicAdd(&red[p0 + 1], a0.y);
        atomicAdd(&red[p0 + 2], a0.z); atomicAdd(&red[p0 + 3], a0.w);
        int p1 = 4 * (sub + 16);
        atomicAdd(&red[p1 + 0], a1.x); atomicAdd(&red[p1 + 1], a1.y);
        atomicAdd(&red[p1 + 2], a1.z); atomicAdd(&red[p1 + 3], a1.w);
        int p2 = 4 * (sub + 32);
        atomicAdd(&red[p2 + 0], a2.x); atomicAdd(&red[p2 + 1], a2.y);
        atomicAdd(&red[p2 + 2], a2.z); atomicAdd(&red[p2 + 3], a2.w);
        int p3 = 4 * (sub + 48);
        atomicAdd(&red[p3 + 0], a3.x); atomicAdd(&red[p3 + 1], a3.y);
        atomicAdd(&red[p3 + 2], a3.z); atomicAdd(&red[p3 + 3], a3.w);
        if (sub < 11) {
            int p4 = 4 * (sub + 64);
            atomicAdd(&red[p4 + 0], a4.x); atomicAdd(&red[p4 + 1], a4.y);
            atomicAdd(&red[p4 + 2], a4.z); atomicAdd(&red[p4 + 3], a4.w);
        }
    }
    __syncthreads();
    for (int i = tid; i < D_; i += 256) atomicAdd(&g_sumvec[b * D_ + i], red[i]);
}

// ---------------- pass2: fused softmax + weighted gather-sum ----------------
__global__ void pass2_kernel(const int* __restrict__ text,
                             const float4* __restrict__ embed4) {
    __shared__ float red[D_];
    __shared__ float swp[L_];      // e*w, pre-normalization
    __shared__ float buf[256];
    int tid = threadIdx.x;
    int b = blockIdx.y;
    for (int i = tid; i < D_; i += 256) red[i] = 0.f;

    // ---- fused softmax over L (redundant per CH block) ----
    float memf  = (float)g_len[b * 3 + 0];
    float start = (float)(g_len[b * 3 + 2] - g_len[b * 3 + 1]);
    float endf  = (float)g_len[b * 3 + 2];
    float qs = g_qs[b];
    float cc = g_sc[0];
    float inv_memf = 1.f / memf;

    float lg[2], wv2[2];
#pragma unroll
    for (int h = 0; h < 2; h++) {
        int l = tid + 256 * h;
        float idx = (float)l;
        float lv = idx < start ? (start - idx) : (idx <= endf ? 0.f : idx - endf);
        float wv = 1.f - lv * inv_memf;
        if (!(idx < memf)) wv = 0.f;
        wv2[h] = wv;
        lg[h] = tanhf(g_dot[b * L_ + l] * wv + cc + qs);
    }
    float m = fmaxf(lg[0], lg[1]);
    buf[tid] = m; __syncthreads();
    for (int s = 128; s; s >>= 1) { if (tid < s) buf[tid] = fmaxf(buf[tid], buf[tid + s]); __syncthreads(); }
    m = buf[0]; __syncthreads();
    float e0 = expf(lg[0] - m), e1 = expf(lg[1] - m);
    swp[tid]       = e0 * wv2[0];
    swp[tid + 256] = e1 * wv2[1];
    buf[tid] = e0 + e1; __syncthreads();
    for (int s = 128; s; s >>= 1) { if (tid < s) buf[tid] += buf[tid + s]; __syncthreads(); }
    float inv = 1.f / buf[0];
    __syncthreads();

    // ---- weighted gather-sum over this block's 64 tokens ----
    int warp = tid >> 5, lane = tid & 31;
    int half = lane >> 4, sub = lane & 15;
    int l0 = blockIdx.x * (L_ / CH_) + warp * 8;
    int last = (sub < 11) ? (sub + 64) : (D4_ - 1);

    float4 a0 = make_float4(0.f,0.f,0.f,0.f), a1 = a0, a2 = a0, a3 = a0, a4 = a0;

#pragma unroll
    for (int pr = 0; pr < 4; pr++) {
        int l = l0 + 2 * pr + half;
        float swv = swp[l] * inv;
        if (swv != 0.f) {
            int tok = text[b * L_ + l];
            const float4* row = embed4 + (long)tok * D4_;
            float4 v0 = row[sub];
            float4 v1 = row[sub + 16];
            float4 v2 = row[sub + 32];
            float4 v3 = row[sub + 48];
            float4 v4 = row[last];
            a0.x = fmaf(swv, v0.x, a0.x); a0.y = fmaf(swv, v0.y, a0.y);
            a0.z = fmaf(swv, v0.z, a0.z); a0.w = fmaf(swv, v0.w, a0.w);
            a1.x = fmaf(swv, v1.x, a1.x); a1.y = fmaf(swv, v1.y, a1.y);
            a1.z = fmaf(swv, v1.z, a1.z); a1.w = fmaf(swv, v1.w, a1.w);
            a2.x = fmaf(swv, v2.x, a2.x); a2.y = fmaf(swv, v2.y, a2.y);
            a2.z = fmaf(swv, v2.z, a2.z); a2.w = fmaf(swv, v2.w, a2.w);
            a3.x = fmaf(swv, v3.x, a3.x); a3.y = fmaf(swv, v3.y, a3.y);
            a3.z = fmaf(swv, v3.z, a3.z); a3.w = fmaf(swv, v3.w, a3.w);
            if (sub < 11) {
                a4.x = fmaf(swv, v4.x, a4.x); a4.y = fmaf(swv, v4.y, a4.y);
                a4.z = fmaf(swv, v4.z, a4.z); a4.w = fmaf(swv, v4.w, a4.w);
            }
        }
    }

    {
        int p0 = 4 * sub;
        atomicAdd(&red[p0 + 0], a0.x); atomicAdd(&red[p0 + 1], a0.y);
        atomicAdd(&red[p0 + 2], a0.z); atomicAdd(&red[p0 + 3], a0.w);
        int p1 = 4 * (sub + 16);
        atomicAdd(&red[p1 + 0], a1.x); atomicAdd(&red[p1 + 1], a1.y);
        atomicAdd(&red[p1 + 2], a1.z); atomicAdd(&red[p1 + 3], a1.w);
        int p2 = 4 * (sub + 32);
        atomicAdd(&red[p2 + 0], a2.x); atomicAdd(&red[p2 + 1], a2.y);
        atomicAdd(&red[p2 + 2], a2.z); atomicAdd(&red[p2 + 3], a2.w);
        int p3 = 4 * (sub + 48);
        atomicAdd(&red[p3 + 0], a3.x); atomicAdd(&red[p3 + 1], a3.y);
        atomicAdd(&red[p3 + 2], a3.z); atomicAdd(&red[p3 + 3], a3.w);
        if (sub < 11) {
            int p4 = 4 * (sub + 64);
            atomicAdd(&red[p4 + 0], a4.x); atomicAdd(&red[p4 + 1], a4.y);
            atomicAdd(&red[p4 + 2], a4.z); atomicAdd(&red[p4 + 3], a4.w);
        }
    }
    __syncthreads();
    for (int i = tid; i < D_; i += 256) atomicAdd(&g_matt[b * D_ + i], red[i]);
}

// ---------------- head ----------------
__global__ void head_kernel(const float* __restrict__ Wk, const float* __restrict__ bk,
                            const float* __restrict__ Wproj, const float* __restrict__ bproj,
                            const float* __restrict__ Wm, const float* __restrict__ bm,
                            const float* __restrict__ Wd, const float* __restrict__ bd,
                            float* __restrict__ out) {
    const int R = 4;
    int b0 = blockIdx.x * R, tid = threadIdx.x;
    __shared__ float s_in[R][D_];
    __shared__ float s_out[R][D_];
    __shared__ float slog[R][P_];

    for (int i = tid; i < R * D_; i += 320)
        s_in[i / D_][i % D_] = g_matt[(b0 + i / D_) * D_ + (i % D_)];
    __syncthreads();

    float acc[R];
    if (tid < D_) {
#pragma unroll
        for (int r = 0; r < R; r++) acc[r] = bk[tid];
#pragma unroll 4
        for (int d = 0; d < D_; d++) {
            float wv = Wk[d * D_ + tid];
#pragma unroll
            for (int r = 0; r < R; r++) acc[r] = fmaf(s_in[r][d], wv, acc[r]);
        }
#pragma unroll
        for (int r = 0; r < R; r++) s_out[r][tid] = acc[r];
    }
    __syncthreads();
    if (tid < D_) {
#pragma unroll
        for (int r = 0; r < R; r++) acc[r] = bproj[tid];
#pragma unroll 4
        for (int d = 0; d < D_; d++) {
            float wv = Wproj[d * D_ + tid];
#pragma unroll
            for (int r = 0; r < R; r++) acc[r] = fmaf(s_out[r][d], wv, acc[r]);
        }
#pragma unroll
        for (int r = 0; r < R; r++) {
            float vs = g_sumvec[(b0 + r) * D_ + tid] / (float)g_len[(b0 + r) * 3 + 0];
            s_in[r][tid] = acc[r] + vs;
        }
    }
    __syncthreads();
    if (tid < D_) {
#pragma unroll
        for (int r = 0; r < R; r++) acc[r] = bm[tid];
#pragma unroll 4
        for (int d = 0; d < D_; d++) {
            float wv = Wm[d * D_ + tid];
#pragma unroll
            for (int r = 0; r < R; r++) acc[r] = fmaf(s_in[r][d], wv, acc[r]);
        }
#pragma unroll
        for (int r = 0; r < R; r++) s_out[r][tid] = tanhf(acc[r]);
    }
    __syncthreads();
    if (tid < R * P_) {
        int r = tid / P_, p = tid % P_;
        float s = bd[p];
        for (int d = 0; d < D_; d++) s = fmaf(s_out[r][d], Wd[d * P_ + p], s);
        slog[r][p] = s;
    }
    __syncthreads();
    if (tid < R) {
        int r = tid;
        float m = fmaxf(slog[r][0], fmaxf(slog[r][1], slog[r][2]));
        float e0 = expf(slog[r][0] - m), e1 = expf(slog[r][1] - m), e2 = expf(slog[r][2] - m);
        float inv = 1.f / (e0 + e1 + e2);
        out[(b0 + r) * P_ + 0] = e0 * inv;
        out[(b0 + r) * P_ + 1] = e1 * inv;
        out[(b0 + r) * P_ + 2] = e2 * inv;
    }
}

extern "C" void kernel_launch(void* const* d_in, const int* in_sizes, int n_in,
                              void* d_out, int out_size) {
    const int*   text   = (const int*)d_in[0];
    const int*   aspect = (const int*)d_in[1];
    const int*   left   = (const int*)d_in[2];
    const float* embed  = (const float*)d_in[3];
    const float* Wx     = (const float*)d_in[4];
    // d_in[5] = Ws (dead in reference)
    const float* Wk     = (const float*)d_in[6];
    const float* bk     = (const float*)d_in[7];
    const float* Wq     = (const float*)d_in[8];
    const float* bq     = (const float*)d_in[9];
    const float* w_mlp  = (const float*)d_in[10];
    const float* Wproj  = (const float*)d_in[11];
    const float* bproj  = (const float*)d_in[12];
    const float* Wm     = (const float*)d_in[13];
    const float* bm     = (const float*)d_in[14];
    const float* Wd     = (const float*)d_in[15];
    const float* bd     = (const float*)d_in[16];
    float* out = (float*)d_out;

    prep_kernel<<<B_, 320>>>(text, aspect, left, embed);
    vecA_kernel<<<31, 320>>>(Wk, bk, Wq, bq, w_mlp);
    mv_kernel<<<30, 320>>>(Wx, 0);
    mv_kernel<<<30, 320>>>(Wx, 1);
    mv_kernel<<<30, 320>>>(Wx, 2);
    qs_kernel<<<26, 320>>>();
    pass1_kernel<<<dim3(CH_, B_), 256>>>(text, (const float4*)embed);
    pass2_kernel<<<dim3(CH_, B_), 256>>>(text, (const float4*)embed);
    head_kernel<<<B_ / 4, 320>>>(Wk, bk, Wproj, bproj, Wm, bm, Wd, bd, out);
}

// round 4
// speedup vs baseline: 1.6978x; 1.3542x over previous
#include <cuda_runtime.h>

#define B_   256
#define L_   512
#define LA_  8
#define LLF_ 64
#define V_   100000
#define D_   300
#define P_   3
#define D4_  75

// ---------------- device scratch ----------------
__device__ __align__(16) float g_asp_e[B_ * D_];
__device__ __align__(16) float g_sumvec[B_ * D_];
__device__ __align__(16) float g_matt[B_ * D_];
__device__ int   g_len[B_ * 3];   // mem_len, asp_len, left_len
__device__ __align__(16) float g_u[D_];
__device__ __align__(16) float g_t0[D_];
__device__ __align__(16) float g_t1[D_];
__device__ __align__(16) float g_p[D_];
__device__ float g_sc[2];         // c = bk.a , constq = bq.b
__device__ float g_qs[B_];

// ---------------- combo: blocks 0..30 vec-part, blocks 31..286 prep-part --------
__global__ void combo_kernel(const int* __restrict__ text,
                             const int* __restrict__ aspect,
                             const int* __restrict__ left,
                             const float* __restrict__ embed,
                             const float* __restrict__ Wk,
                             const float* __restrict__ bk,
                             const float* __restrict__ Wq,
                             const float* __restrict__ bq,
                             const float* __restrict__ w_mlp) {
    int tid = threadIdx.x;
    if (blockIdx.x < 31) {
        // ---- vecA: u = Wk@a, t0 = Wq@b, scalars ----
        int warp = tid >> 5, lane = tid & 31;
        int gw = blockIdx.x * 10 + warp;
        if (gw < D_) {
            float u = 0.f, q = 0.f;
            int base = gw * D_;
#pragma unroll
            for (int k = 0; k < 9; k++) {
                int j = lane + 32 * k;
                u = fmaf(Wk[base + j], w_mlp[j], u);
                q = fmaf(Wq[base + j], w_mlp[D_ + j], q);
            }
            if (lane < 12) {
                int j = 288 + lane;
                u = fmaf(Wk[base + j], w_mlp[j], u);
                q = fmaf(Wq[base + j], w_mlp[D_ + j], q);
            }
#pragma unroll
            for (int off = 16; off; off >>= 1) {
                u += __shfl_xor_sync(0xffffffffu, u, off);
                q += __shfl_xor_sync(0xffffffffu, q, off);
            }
            if (lane == 0) { g_u[gw] = u; g_t0[gw] = q; }
        } else if (gw == D_ || gw == D_ + 1) {
            const float* v1 = (gw == D_) ? bk : bq;
            const float* v2 = (gw == D_) ? w_mlp : (w_mlp + D_);
            float s = 0.f;
            for (int j = lane; j < D_; j += 32) s = fmaf(v1[j], v2[j], s);
#pragma unroll
            for (int off = 16; off; off >>= 1) s += __shfl_xor_sync(0xffffffffu, s, off);
            if (lane == 0) g_sc[gw - D_] = s;
        }
    } else {
        // ---- prep: lengths + aspect embedding ----
        int b = blockIdx.x - 31;
        __shared__ int cnt[3];
        if (tid < 3) cnt[tid] = 0;
        __syncthreads();
        int c0 = 0;
        for (int l = tid; l < L_; l += 320) c0 += (text[b * L_ + l] != 0);
        int c1 = (tid < LA_) ? (aspect[b * LA_ + tid] != 0) : 0;
        int c2 = 0;
        for (int l = tid; l < LLF_; l += 320) c2 += (left[b * LLF_ + l] != 0);
        if (c0) atomicAdd(&cnt[0], c0);
        if (c1) atomicAdd(&cnt[1], c1);
        if (c2) atomicAdd(&cnt[2], c2);
        __syncthreads();
        if (tid < 3) g_len[b * 3 + tid] = cnt[tid];
        if (tid < D_) {
            float s = 0.f;
#pragma unroll
            for (int j = 0; j < LA_; j++) {
                int tok = aspect[b * LA_ + j];
                s += embed[(long)tok * D_ + tid];
            }
            g_asp_e[b * D_ + tid] = s / (float)cnt[1];
        }
    }
}

// ---------------- matvec: out = Wx @ in (warp per row, unrolled) ----------------
__global__ void mv_kernel(const float* __restrict__ Wx, int step) {
    const float* in  = (step == 1) ? g_t1 : g_t0;
    float*       out = (step == 0) ? g_t1 : ((step == 1) ? g_t0 : g_p);
    int warp = threadIdx.x >> 5, lane = threadIdx.x & 31;
    int row = blockIdx.x * 10 + warp;
    if (row >= D_) return;
    int base = row * D_;
    float s = 0.f;
#pragma unroll
    for (int k = 0; k < 9; k++) {
        int j = lane + 32 * k;
        s = fmaf(Wx[base + j], in[j], s);
    }
    if (lane < 12) s = fmaf(Wx[base + 288 + lane], in[288 + lane], s);
#pragma unroll
    for (int off = 16; off; off >>= 1) s += __shfl_xor_sync(0xffffffffu, s, off);
    if (lane == 0) out[row] = s;
}

// ---------------- qs[b] = asp_e[b]·p + constq ----------------
__global__ void qs_kernel() {
    int warp = threadIdx.x >> 5, lane = threadIdx.x & 31;
    int b = blockIdx.x * 10 + warp;
    if (b >= B_) return;
    int base = b * D_;
    float s = 0.f;
#pragma unroll
    for (int k = 0; k < 9; k++) {
        int j = lane + 32 * k;
        s = fmaf(g_asp_e[base + j], g_p[j], s);
    }
    if (lane < 12) s = fmaf(g_asp_e[base + 288 + lane], g_p[288 + lane], s);
#pragma unroll
    for (int off = 16; off; off >>= 1) s += __shfl_xor_sync(0xffffffffu, s, off);
    if (lane == 0) g_qs[b] = s + g_sc[1];
}

// ---------------- fused: dots + raw sum + softmax + weighted gather ------------
// one block per batch row, 512 threads (16 warps x 32 tokens)
__global__ void __launch_bounds__(512, 2)
fused_kernel(const int* __restrict__ text, const float4* __restrict__ embed4) {
    __shared__ float4 su[D4_ + 1];
    __shared__ float red[D_];
    __shared__ float sc[L_];      // dots, then score*w
    __shared__ float rbuf[32];
    int tid = threadIdx.x, b = blockIdx.x;

    if (tid < D4_) su[tid] = reinterpret_cast<const float4*>(g_u)[tid];
    if (tid == D4_) su[D4_] = make_float4(0.f, 0.f, 0.f, 0.f);
    if (tid < D_) red[tid] = 0.f;
    __syncthreads();

    int warp = tid >> 5, lane = tid & 31;
    int half = lane >> 4, sub = lane & 15;
    int l0 = warp * 32;
    int last = (sub < 11) ? (sub + 64) : (D4_ - 1);

    float4 u0 = su[sub], u1 = su[sub + 16], u2 = su[sub + 32], u3 = su[sub + 48];
    float4 u4 = (sub < 11) ? su[sub + 64] : make_float4(0.f, 0.f, 0.f, 0.f);

    float4 a0 = make_float4(0.f,0.f,0.f,0.f), a1 = a0, a2 = a0, a3 = a0, a4 = a0;

    // ---- phase 1: dots + raw sum ----
#pragma unroll 4
    for (int it = 0; it < 16; it++) {
        int l = l0 + 2 * it + half;
        int tok = text[b * L_ + l];
        const float4* row = embed4 + (long)tok * D4_;
        float4 v0 = row[sub];
        float4 v1 = row[sub + 16];
        float4 v2 = row[sub + 32];
        float4 v3 = row[sub + 48];
        float4 v4 = row[last];
        if (sub >= 11) v4 = make_float4(0.f, 0.f, 0.f, 0.f);

        float d = v0.x*u0.x + v0.y*u0.y + v0.z*u0.z + v0.w*u0.w
                + v1.x*u1.x + v1.y*u1.y + v1.z*u1.z + v1.w*u1.w
                + v2.x*u2.x + v2.y*u2.y + v2.z*u2.z + v2.w*u2.w
                + v3.x*u3.x + v3.y*u3.y + v3.z*u3.z + v3.w*u3.w
                + v4.x*u4.x + v4.y*u4.y + v4.z*u4.z + v4.w*u4.w;

        a0.x += v0.x; a0.y += v0.y; a0.z += v0.z; a0.w += v0.w;
        a1.x += v1.x; a1.y += v1.y; a1.z += v1.z; a1.w += v1.w;
        a2.x += v2.x; a2.y += v2.y; a2.z += v2.z; a2.w += v2.w;
        a3.x += v3.x; a3.y += v3.y; a3.z += v3.z; a3.w += v3.w;
        a4.x += v4.x; a4.y += v4.y; a4.z += v4.z; a4.w += v4.w;

#pragma unroll
        for (int off = 8; off; off >>= 1) d += __shfl_xor_sync(0xffffffffu, d, off);
        if (sub == 0) sc[l] = d;
    }
    // combine halves: lanes 0-15 end up with the full warp partial
#pragma unroll
    for (int c = 0; c < 1; c++) { }
    a0.x += __shfl_xor_sync(0xffffffffu, a0.x, 16); a0.y += __shfl_xor_sync(0xffffffffu, a0.y, 16);
    a0.z += __shfl_xor_sync(0xffffffffu, a0.z, 16); a0.w += __shfl_xor_sync(0xffffffffu, a0.w, 16);
    a1.x += __shfl_xor_sync(0xffffffffu, a1.x, 16); a1.y += __shfl_xor_sync(0xffffffffu, a1.y, 16);
    a1.z += __shfl_xor_sync(0xffffffffu, a1.z, 16); a1.w += __shfl_xor_sync(0xffffffffu, a1.w, 16);
    a2.x += __shfl_xor_sync(0xffffffffu, a2.x, 16); a2.y += __shfl_xor_sync(0xffffffffu, a2.y, 16);
    a2.z += __shfl_xor_sync(0xffffffffu, a2.z, 16); a2.w += __shfl_xor_sync(0xffffffffu, a2.w, 16);
    a3.x += __shfl_xor_sync(0xffffffffu, a3.x, 16); a3.y += __shfl_xor_sync(0xffffffffu, a3.y, 16);
    a3.z += __shfl_xor_sync(0xffffffffu, a3.z, 16); a3.w += __shfl_xor_sync(0xffffffffu, a3.w, 16);
    a4.x += __shfl_xor_sync(0xffffffffu, a4.x, 16); a4.y += __shfl_xor_sync(0xffffffffu, a4.y, 16);
    a4.z += __shfl_xor_sync(0xffffffffu, a4.z, 16); a4.w += __shfl_xor_sync(0xffffffffu, a4.w, 16);
    if (half == 0) {
        int p0 = 4 * sub;
        atomicAdd(&red[p0 + 0], a0.x); atomicAdd(&red[p0 + 1], a0.y);
        atomicAdd(&red[p0 + 2], a0.z); atomicAdd(&red[p0 + 3], a0.w);
        int p1 = 4 * (sub + 16);
        atomicAdd(&red[p1 + 0], a1.x); atomicAdd(&red[p1 + 1], a1.y);
        atomicAdd(&red[p1 + 2], a1.z); atomicAdd(&red[p1 + 3], a1.w);
        int p2 = 4 * (sub + 32);
        atomicAdd(&red[p2 + 0], a2.x); atomicAdd(&red[p2 + 1], a2.y);
        atomicAdd(&red[p2 + 2], a2.z); atomicAdd(&red[p2 + 3], a2.w);
        int p3 = 4 * (sub + 48);
        atomicAdd(&red[p3 + 0], a3.x); atomicAdd(&red[p3 + 1], a3.y);
        atomicAdd(&red[p3 + 2], a3.z); atomicAdd(&red[p3 + 3], a3.w);
        if (sub < 11) {
            int p4 = 4 * (sub + 64);
            atomicAdd(&red[p4 + 0], a4.x); atomicAdd(&red[p4 + 1], a4.y);
            atomicAdd(&red[p4 + 2], a4.z); atomicAdd(&red[p4 + 3], a4.w);
        }
    }
    __syncthreads();
    if (tid < D_) { g_sumvec[b * D_ + tid] = red[tid]; red[tid] = 0.f; }

    // ---- softmax over L in-block ----
    float memf  = (float)g_len[b * 3 + 0];
    float start = (float)(g_len[b * 3 + 2] - g_len[b * 3 + 1]);
    float endf  = (float)g_len[b * 3 + 2];
    float qs = g_qs[b], cc = g_sc[0];
    float inv_memf = 1.f / memf;

    float idx = (float)tid;
    float lv = idx < start ? (start - idx) : (idx <= endf ? 0.f : idx - endf);
    float wv = 1.f - lv * inv_memf;
    if (!(idx < memf)) wv = 0.f;
    float logit = tanhf(sc[tid] * wv + cc + qs);

    float m = logit;
#pragma unroll
    for (int off = 16; off; off >>= 1) m = fmaxf(m, __shfl_xor_sync(0xffffffffu, m, off));
    if (lane == 0) rbuf[warp] = m;
    __syncthreads();
    if (warp == 0) {
        float mm = (lane < 16) ? rbuf[lane] : -1e30f;
#pragma unroll
        for (int off = 16; off; off >>= 1) mm = fmaxf(mm, __shfl_xor_sync(0xffffffffu, mm, off));
        if (lane == 0) rbuf[16] = mm;
    }
    __syncthreads();
    m = rbuf[16];
    float e = expf(logit - m);
    float s = e;
#pragma unroll
    for (int off = 16; off; off >>= 1) s += __shfl_xor_sync(0xffffffffu, s, off);
    if (lane == 0) rbuf[warp] = s;
    __syncthreads();
    if (warp == 0) {
        float ss = (lane < 16) ? rbuf[lane] : 0.f;
#pragma unroll
        for (int off = 16; off; off >>= 1) ss += __shfl_xor_sync(0xffffffffu, ss, off);
        if (lane == 0) rbuf[17] = ss;
    }
    __syncthreads();
    float inv = 1.f / rbuf[17];
    sc[tid] = e * inv * wv;     // each thread overwrites its own slot
    __syncthreads();

    // ---- phase 2: weighted gather (rows hot in L1/L2) ----
    a0 = make_float4(0.f,0.f,0.f,0.f); a1 = a0; a2 = a0; a3 = a0; a4 = a0;
#pragma unroll 4
    for (int it = 0; it < 16; it++) {
        int l = l0 + 2 * it + half;
        float swv = sc[l];
        if (swv != 0.f) {
            int tok = text[b * L_ + l];
            const float4* row = embed4 + (long)tok * D4_;
            float4 v0 = row[sub];
            float4 v1 = row[sub + 16];
            float4 v2 = row[sub + 32];
            float4 v3 = row[sub + 48];
            float4 v4 = row[last];
            a0.x = fmaf(swv, v0.x, a0.x); a0.y = fmaf(swv, v0.y, a0.y);
            a0.z = fmaf(swv, v0.z, a0.z); a0.w = fmaf(swv, v0.w, a0.w);
            a1.x = fmaf(swv, v1.x, a1.x); a1.y = fmaf(swv, v1.y, a1.y);
            a1.z = fmaf(swv, v1.z, a1.z); a1.w = fmaf(swv, v1.w, a1.w);
            a2.x = fmaf(swv, v2.x, a2.x); a2.y = fmaf(swv, v2.y, a2.y);
            a2.z = fmaf(swv, v2.z, a2.z); a2.w = fmaf(swv, v2.w, a2.w);
            a3.x = fmaf(swv, v3.x, a3.x); a3.y = fmaf(swv, v3.y, a3.y);
            a3.z = fmaf(swv, v3.z, a3.z); a3.w = fmaf(swv, v3.w, a3.w);
            if (sub < 11) {
                a4.x = fmaf(swv, v4.x, a4.x); a4.y = fmaf(swv, v4.y, a4.y);
                a4.z = fmaf(swv, v4.z, a4.z); a4.w = fmaf(swv, v4.w, a4.w);
            }
        }
    }
    a0.x += __shfl_xor_sync(0xffffffffu, a0.x, 16); a0.y += __shfl_xor_sync(0xffffffffu, a0.y, 16);
    a0.z += __shfl_xor_sync(0xffffffffu, a0.z, 16); a0.w += __shfl_xor_sync(0xffffffffu, a0.w, 16);
    a1.x += __shfl_xor_sync(0xffffffffu, a1.x, 16); a1.y += __shfl_xor_sync(0xffffffffu, a1.y, 16);
    a1.z += __shfl_xor_sync(0xffffffffu, a1.z, 16); a1.w += __shfl_xor_sync(0xffffffffu, a1.w, 16);
    a2.x += __shfl_xor_sync(0xffffffffu, a2.x, 16); a2.y += __shfl_xor_sync(0xffffffffu, a2.y, 16);
    a2.z += __shfl_xor_sync(0xffffffffu, a2.z, 16); a2.w += __shfl_xor_sync(0xffffffffu, a2.w, 16);
    a3.x += __shfl_xor_sync(0xffffffffu, a3.x, 16); a3.y += __shfl_xor_sync(0xffffffffu, a3.y, 16);
    a3.z += __shfl_xor_sync(0xffffffffu, a3.z, 16); a3.w += __shfl_xor_sync(0xffffffffu, a3.w, 16);
    a4.x += __shfl_xor_sync(0xffffffffu, a4.x, 16); a4.y += __shfl_xor_sync(0xffffffffu, a4.y, 16);
    a4.z += __shfl_xor_sync(0xffffffffu, a4.z, 16); a4.w += __shfl_xor_sync(0xffffffffu, a4.w, 16);
    if (half == 0) {
        int p0 = 4 * sub;
        atomicAdd(&red[p0 + 0], a0.x); atomicAdd(&red[p0 + 1], a0.y);
        atomicAdd(&red[p0 + 2], a0.z); atomicAdd(&red[p0 + 3], a0.w);
        int p1 = 4 * (sub + 16);
        atomicAdd(&red[p1 + 0], a1.x); atomicAdd(&red[p1 + 1], a1.y);
        atomicAdd(&red[p1 + 2], a1.z); atomicAdd(&red[p1 + 3], a1.w);
        int p2 = 4 * (sub + 32);
        atomicAdd(&red[p2 + 0], a2.x); atomicAdd(&red[p2 + 1], a2.y);
        atomicAdd(&red[p2 + 2], a2.z); atomicAdd(&red[p2 + 3], a2.w);
        int p3 = 4 * (sub + 48);
        atomicAdd(&red[p3 + 0], a3.x); atomicAdd(&red[p3 + 1], a3.y);
        atomicAdd(&red[p3 + 2], a3.z); atomicAdd(&red[p3 + 3], a3.w);
        if (sub < 11) {
            int p4 = 4 * (sub + 64);
            atomicAdd(&red[p4 + 0], a4.x); atomicAdd(&red[p4 + 1], a4.y);
            atomicAdd(&red[p4 + 2], a4.z); atomicAdd(&red[p4 + 3], a4.w);
        }
    }
    __syncthreads();
    if (tid < D_) g_matt[b * D_ + tid] = red[tid];
}

// ---------------- head ----------------
__global__ void head_kernel(const float* __restrict__ Wk, const float* __restrict__ bk,
                            const float* __restrict__ Wproj, const float* __restrict__ bproj,
                            const float* __restrict__ Wm, const float* __restrict__ bm,
                            const float* __restrict__ Wd, const float* __restrict__ bd,
                            float* __restrict__ out) {
    const int R = 4;
    int b0 = blockIdx.x * R, tid = threadIdx.x;
    __shared__ float s_in[R][D_];
    __shared__ float s_out[R][D_];
    __shared__ float slog[R][P_];

    for (int i = tid; i < R * D_; i += 320)
        s_in[i / D_][i % D_] = g_matt[(b0 + i / D_) * D_ + (i % D_)];
    __syncthreads();

    float acc[R];
    if (tid < D_) {
#pragma unroll
        for (int r = 0; r < R; r++) acc[r] = bk[tid];
#pragma unroll 4
        for (int d = 0; d < D_; d++) {
            float wv = Wk[d * D_ + tid];
#pragma unroll
            for (int r = 0; r < R; r++) acc[r] = fmaf(s_in[r][d], wv, acc[r]);
        }
#pragma unroll
        for (int r = 0; r < R; r++) s_out[r][tid] = acc[r];
    }
    __syncthreads();
    if (tid < D_) {
#pragma unroll
        for (int r = 0; r < R; r++) acc[r] = bproj[tid];
#pragma unroll 4
        for (int d = 0; d < D_; d++) {
            float wv = Wproj[d * D_ + tid];
#pragma unroll
            for (int r = 0; r < R; r++) acc[r] = fmaf(s_out[r][d], wv, acc[r]);
        }
#pragma unroll
        for (int r = 0; r < R; r++) {
            float vs = g_sumvec[(b0 + r) * D_ + tid] / (float)g_len[(b0 + r) * 3 + 0];
            s_in[r][tid] = acc[r] + vs;
        }
    }
    __syncthreads();
    if (tid < D_) {
#pragma unroll
        for (int r = 0; r < R; r++) acc[r] = bm[tid];
#pragma unroll 4
        for (int d = 0; d < D_; d++) {
            float wv = Wm[d * D_ + tid];
#pragma unroll
            for (int r = 0; r < R; r++) acc[r] = fmaf(s_in[r][d], wv, acc[r]);
        }
#pragma unroll
        for (int r = 0; r < R; r++) s_out[r][tid] = tanhf(acc[r]);
    }
    __syncthreads();
    if (tid < R * P_) {
        int r = tid / P_, p = tid % P_;
        float s = bd[p];
        for (int d = 0; d < D_; d++) s = fmaf(s_out[r][d], Wd[d * P_ + p], s);
        slog[r][p] = s;
    }
    __syncthreads();
    if (tid < R) {
        int r = tid;
        float m = fmaxf(slog[r][0], fmaxf(slog[r][1], slog[r][2]));
        float e0 = expf(slog[r][0] - m), e1 = expf(slog[r][1] - m), e2 = expf(slog[r][2] - m);
        float inv = 1.f / (e0 + e1 + e2);
        out[(b0 + r) * P_ + 0] = e0 * inv;
        out[(b0 + r) * P_ + 1] = e1 * inv;
        out[(b0 + r) * P_ + 2] = e2 * inv;
    }
}

extern "C" void kernel_launch(void* const* d_in, const int* in_sizes, int n_in,
                              void* d_out, int out_size) {
    const int*   text   = (const int*)d_in[0];
    const int*   aspect = (const int*)d_in[1];
    const int*   left   = (const int*)d_in[2];
    const float* embed  = (const float*)d_in[3];
    const float* Wx     = (const float*)d_in[4];
    // d_in[5] = Ws (dead in reference)
    const float* Wk     = (const float*)d_in[6];
    const float* bk     = (const float*)d_in[7];
    const float* Wq     = (const float*)d_in[8];
    const float* bq     = (const float*)d_in[9];
    const float* w_mlp  = (const float*)d_in[10];
    const float* Wproj  = (const float*)d_in[11];
    const float* bproj  = (const float*)d_in[12];
    const float* Wm     = (const float*)d_in[13];
    const float* bm     = (const float*)d_in[14];
    const float* Wd     = (const float*)d_in[15];
    const float* bd     = (const float*)d_in[16];
    float* out = (float*)d_out;

    combo_kernel<<<287, 320>>>(text, aspect, left, embed, Wk, bk, Wq, bq, w_mlp);
    mv_kernel<<<30, 320>>>(Wx, 0);
    mv_kernel<<<30, 320>>>(Wx, 1);
    mv_kernel<<<30, 320>>>(Wx, 2);
    qs_kernel<<<26, 320>>>();
    fused_kernel<<<B_, 512>>>(text, (const float4*)embed);
    head_kernel<<<B_ / 4, 320>>>(Wk, bk, Wproj, bproj, Wm, bm, Wd, bd, out);
}